// round 14
// baseline (speedup 1.0000x reference)
#include <cuda_runtime.h>
#include <cuda_fp16.h>
#include <math.h>
#include <stdint.h>

#define NN 20000
#define ETOT 150000
#define LPART 75000
#define FINC 256
#define HC 512
#define H2C 1024

// ---------------- static device scratch ----------------
__device__ __half g_sfdf[NN * 2048];
__device__ __half g_x1[NN * HC];
__device__ __half g_xh[NN * FINC];
__device__ __half g_ob[2 * NN * HC];
__device__ __half g_hb[NN * 2048];
__device__ __half g_wcat[2048 * FINC];
__device__ __half g_w01[2 * H2C * HC];
__device__ __half g_w02c[HC * 2048];
__device__ __half g_w11[2 * H2C * HC];
__device__ __half g_w12c[HC * 2048];
__device__ int g_rowptr[2][NN + 1];
__device__ int g_cursor[2][NN];
__device__ int g_eidx[2][LPART];

// ---------------- CSR build ----------------
__global__ void k_zero_int(int* p, int n) {
    int i = blockIdx.x * blockDim.x + threadIdx.x;
    if (i < n) p[i] = 0;
}

__global__ void k_count_deg2(const int* __restrict__ dstBoth, int* __restrict__ deg) {
    int i = blockIdx.x * blockDim.x + threadIdx.x;
    if (i < 2 * LPART) {
        int p = i / LPART;
        atomicAdd(&deg[p * NN + dstBoth[i]], 1);
    }
}

__global__ void k_scan2(const int* __restrict__ deg, int* __restrict__ rowptr) {
    __shared__ int sbuf[1024];
    __shared__ int carry;
    int p = blockIdx.x;
    const int* d = deg + p * NN;
    int* rp = rowptr + p * (NN + 1);
    int t = threadIdx.x;
    if (t == 0) { carry = 0; rp[0] = 0; }
    __syncthreads();
    for (int base = 0; base < NN; base += 1024) {
        int v = (base + t < NN) ? d[base + t] : 0;
        sbuf[t] = v;
        __syncthreads();
        for (int off = 1; off < 1024; off <<= 1) {
            int nv = (t >= off) ? sbuf[t - off] : 0;
            __syncthreads();
            sbuf[t] += nv;
            __syncthreads();
        }
        if (base + t < NN) rp[base + t + 1] = carry + sbuf[t];
        __syncthreads();
        if (t == 0) carry += sbuf[1023];
        __syncthreads();
    }
}

__global__ void k_copy_rp2(const int* __restrict__ rowptr, int* __restrict__ cursor) {
    int i = blockIdx.x * blockDim.x + threadIdx.x;
    if (i < 2 * NN) {
        int p = i / NN, r = i % NN;
        cursor[i] = rowptr[p * (NN + 1) + r];
    }
}

__global__ void k_scatter2(const int* __restrict__ dstBoth, int* __restrict__ cursor,
                           int* __restrict__ eidx) {
    int i = blockIdx.x * blockDim.x + threadIdx.x;
    if (i < 2 * LPART) {
        int p = i / LPART;
        int pos = atomicAdd(&cursor[p * NN + dstBoth[i]], 1);
        eidx[p * LPART + pos] = i - p * LPART;
    }
}

__global__ void k_sort_buckets2(const int* __restrict__ rowptr, int* __restrict__ eidx) {
    int i = blockIdx.x * blockDim.x + threadIdx.x;
    if (i >= 2 * NN) return;
    int p = i / NN, node = i % NN;
    const int* rp = rowptr + p * (NN + 1);
    int* ex = eidx + p * LPART;
    int a = rp[node], b = rp[node + 1];
    for (int q = a + 1; q < b; q++) {
        int key = ex[q];
        int j = q - 1;
        while (j >= a && ex[j] > key) { ex[j + 1] = ex[j]; j--; }
        ex[j + 1] = key;
    }
}

// ---------------- fused conversions ----------------
__global__ void k_half(const float* __restrict__ s, __half* __restrict__ h, int n) {
    int i = blockIdx.x * blockDim.x + threadIdx.x;
    if (i < n) h[i] = __float2half(s[i]);
}

__global__ void k_half_cat2(const float* __restrict__ ssrc, const float* __restrict__ sdst,
                            __half* __restrict__ wcat) {
    int i = blockIdx.x * blockDim.x + threadIdx.x;
    int NEL = 2 * HC * FINC;
    if (i >= 2 * NEL) return;
    int which = i >= NEL;
    int ii = i - which * NEL;
    const float* s = which ? sdst : ssrc;
    int off = which ? 512 : 0;
    int l = ii >> 17;
    int rem = ii & 131071;
    int rr = rem >> 8;
    int c = rem & 255;
    wcat[((l * 1024 + off + rr) << 8) + c] = __float2half(s[ii]);
}

__global__ void k_half2x(const float* __restrict__ s0, __half* __restrict__ h0,
                         const float* __restrict__ s1, __half* __restrict__ h1, int n) {
    int i = blockIdx.x * blockDim.x + threadIdx.x;
    if (i < n) h0[i] = __float2half(s0[i]);
    else if (i < 2 * n) h1[i - n] = __float2half(s1[i - n]);
}

__global__ void k_half_w2cat2(const float* __restrict__ s0, __half* __restrict__ w0,
                              const float* __restrict__ s1, __half* __restrict__ w1) {
    int i = blockIdx.x * blockDim.x + threadIdx.x;
    int NEL = 2 * HC * H2C;
    if (i >= 2 * NEL) return;
    int which = i >= NEL;
    int ii = i - which * NEL;
    const float* s = which ? s1 : s0;
    __half* w = which ? w1 : w0;
    int l = ii >> 19;
    int rem = ii & 524287;
    int n = rem >> 10;
    int kk = rem & 1023;
    w[n * 2048 + (l << 10) + kk] = __float2half(s[ii]);
}

// ---------------- merged per-layer edge softmax aggregation (prefetched) ---------
__global__ __launch_bounds__(128) void k_agg2(
    const __half* __restrict__ sf_base, int sf_loff, int sstr,
    const __half* __restrict__ df_base, int df_loff, int dstr,
    const float* __restrict__ WeBoth,
    const float* __restrict__ ea,
    const int* __restrict__ srcBoth,
    const int* __restrict__ rowptr,
    const int* __restrict__ eidx,
    __half* __restrict__ oh)
{
    __shared__ float wsh[HC];
    int t = threadIdx.x;
    int pblk = (blockIdx.x * 4) / NN;
    for (int i = t; i < HC; i += 128) wsh[i] = WeBoth[pblk * HC + i];
    __syncthreads();

    int warp = t >> 5, lane = t & 31;
    int gw = blockIdx.x * 4 + warp;
    if (gw >= 2 * NN) return;
    int p = gw >= NN;
    int node = gw - p * NN;

    const int4* sfeat = (const int4*)(sf_base + (size_t)p * sf_loff);
    const int4* dfeat = (const int4*)(df_base + (size_t)p * df_loff);
    int s4 = sstr >> 3, d4 = dstr >> 3;
    const float* eap = ea + (size_t)p * LPART;
    const int* srcp = srcBoth + (size_t)p * LPART;
    const int* rp = rowptr + p * (NN + 1);
    const int* ex = eidx + (size_t)p * LPART;

    float wv[16];
#pragma unroll
    for (int k = 0; k < 8; k++) {
        wv[k] = wsh[8 * lane + k];
        wv[8 + k] = wsh[8 * (lane + 32) + k];
    }

    float m[16], s[16], tt[16];
#pragma unroll
    for (int j = 0; j < 16; j++) { m[j] = -INFINITY; s[j] = 0.f; tt[j] = 0.f; }

    int e0 = rp[node], e1 = rp[node + 1];
    if (e0 < e1) {
        // prime first edge
        int eid = ex[e0];
        float a = eap[eid];
        const int4* row = sfeat + (size_t)srcp[eid] * s4;
        int4 v0 = row[lane];
        int4 v1 = row[lane + 32];

        for (int e = e0; e < e1; e++) {
            // prefetch next edge before compute
            int4 nv0, nv1;
            float na = 0.f;
            if (e + 1 < e1) {
                int neid = ex[e + 1];
                na = eap[neid];
                const int4* nrow = sfeat + (size_t)srcp[neid] * s4;
                nv0 = nrow[lane];
                nv1 = nrow[lane + 32];
            }

            const __half2* h0 = (const __half2*)&v0;
            const __half2* h1 = (const __half2*)&v1;
#pragma unroll
            for (int q = 0; q < 4; q++) {
                float2 f0 = __half22float2(h0[q]);
                float2 f1 = __half22float2(h1[q]);
                float vals[4] = {f0.x, f0.y, f1.x, f1.y};
                int js[4] = {2 * q, 2 * q + 1, 8 + 2 * q, 8 + 2 * q + 1};
#pragma unroll
                for (int u = 0; u < 4; u++) {
                    int j = js[u];
                    float msg = fmaxf(vals[u] + a * wv[j], 0.f) + 1e-7f;
                    float mn = fmaxf(m[j], msg);
                    float scale = __expf(m[j] - mn);
                    float pr = __expf(msg - mn);
                    s[j] = s[j] * scale + pr;
                    tt[j] = tt[j] * scale + msg * pr;
                    m[j] = mn;
                }
            }
            v0 = nv0;
            v1 = nv1;
            a = na;
        }
    }

    const int4* drow = dfeat + (size_t)node * d4;
    int4 d0 = drow[lane];
    int4 d1 = drow[lane + 32];
    const __half2* dh0 = (const __half2*)&d0;
    const __half2* dh1 = (const __half2*)&d1;

    int4 o0, o1;
    __half2* oh0 = (__half2*)&o0;
    __half2* oh1 = (__half2*)&o1;
#pragma unroll
    for (int q = 0; q < 4; q++) {
        float2 dv0 = __half22float2(dh0[q]);
        float2 dv1 = __half22float2(dh1[q]);
        float a0 = tt[2 * q] / (s[2 * q] + 1e-16f) + dv0.x;
        float a1 = tt[2 * q + 1] / (s[2 * q + 1] + 1e-16f) + dv0.y;
        float b0 = tt[8 + 2 * q] / (s[8 + 2 * q] + 1e-16f) + dv1.x;
        float b1 = tt[8 + 2 * q + 1] / (s[8 + 2 * q + 1] + 1e-16f) + dv1.y;
        oh0[q] = __floats2half2_rn(a0, a1);
        oh1[q] = __floats2half2_rn(b0, b1);
    }
    int4* orow = (int4*)(oh + ((size_t)p * NN + node) * HC);
    orow[lane] = o0;
    orow[lane + 32] = o1;
}

// ---------------- fp16 GEMM, templated on M-tile: BM = AT*32 ---------------------
// AT=4: 128x128x64 (default). AT=2: 64x128x64 (for short-grid W2 GEMMs).
#define BN 128
#define BK 64
#define BKH 72
#define STG 3
#define TILE_B_BYTES (BN * BKH * 2)           // 18432

__device__ __forceinline__ void mma_f16(float* c, const uint32_t* a, uint32_t b0, uint32_t b1) {
    asm volatile(
        "mma.sync.aligned.m16n8k16.row.col.f32.f16.f16.f32 "
        "{%0,%1,%2,%3}, {%4,%5,%6,%7}, {%8,%9}, {%0,%1,%2,%3};"
        : "+f"(c[0]), "+f"(c[1]), "+f"(c[2]), "+f"(c[3])
        : "r"(a[0]), "r"(a[1]), "r"(a[2]), "r"(a[3]), "r"(b0), "r"(b1));
}

__device__ __forceinline__ void ldsm4(uint32_t* r, uint32_t addr) {
    asm volatile("ldmatrix.sync.aligned.m8n8.x4.shared.b16 {%0,%1,%2,%3}, [%4];"
                 : "=r"(r[0]), "=r"(r[1]), "=r"(r[2]), "=r"(r[3]) : "r"(addr));
}

__device__ __forceinline__ void cp16(uint32_t saddr, const void* gaddr, int srcbytes) {
    asm volatile("cp.async.cg.shared.global [%0], [%1], 16, %2;"
                 :: "r"(saddr), "l"(gaddr), "r"(srcbytes));
}

template <int AT>
__global__ __launch_bounds__(256, 2) void k_hgemm(
    const __half* __restrict__ A0, const __half* __restrict__ A1, int nsplit,
    const __half* __restrict__ B,
    int M, int K, int Ncols, int mode,
    const float* __restrict__ gv, const float* __restrict__ bv,
    const float* __restrict__ mv, const float* __restrict__ vv,
    float* __restrict__ Cf, __half* __restrict__ Ch)
{
    constexpr int BMt = AT * 32;
    constexpr int TILE_A_BYTES = BMt * BKH * 2;
    constexpr int STAGE_BYTES = TILE_A_BYTES + TILE_B_BYTES;

    extern __shared__ __align__(128) char smc[];
    uint32_t sbase = (uint32_t)__cvta_generic_to_shared(smc);

    int tid = threadIdx.x;
    int tileM = blockIdx.y * BMt, tileN = blockIdx.x * BN;
    const __half* A = (tileN >= nsplit) ? A1 : A0;
    int warp = tid >> 5, lane = tid & 31;
    int g8 = lane >> 2, t4 = lane & 3;
    int wm = (warp & 1) * (AT * 16);
    int wn = (warp >> 1) * 32;

    const __half* Ag = A + (size_t)tileM * K;
    const __half* Bg = B + (size_t)tileN * K;

    // staging: A = BMt*8 chunks (AT per thread), B = 1024 chunks (4 per thread)
    int rA[AT], cA[AT], szA[AT];
    uint32_t dA[AT];
#pragma unroll
    for (int i = 0; i < AT; i++) {
        int q = tid + i * 256;
        rA[i] = q >> 3;
        cA[i] = (q & 7) * 8;
        szA[i] = (tileM + rA[i]) < M ? 16 : 0;
        dA[i] = sbase + (uint32_t)((rA[i] * BKH + cA[i]) * 2);
    }
    int rB[4], cB[4];
    uint32_t dB[4];
#pragma unroll
    for (int i = 0; i < 4; i++) {
        int q = tid + i * 256;
        rB[i] = q >> 3;
        cB[i] = (q & 7) * 8;
        dB[i] = sbase + (uint32_t)(TILE_A_BYTES + (rB[i] * BKH + cB[i]) * 2);
    }

    int mrowA = (lane & 7) + ((lane >> 3) & 1) * 8;
    int kcolA = (lane >> 4) * 8;
    uint32_t aOff = (uint32_t)(((wm + mrowA) * BKH + kcolA) * 2);
    int nrowB = ((lane >> 4) & 1) * 8 + (lane & 7);
    int kcolB = ((lane >> 3) & 1) * 8;
    uint32_t bOff = (uint32_t)(TILE_A_BYTES + ((wn + nrowB) * BKH + kcolB) * 2);

    float acc[AT][4][4];
#pragma unroll
    for (int i = 0; i < AT; i++)
#pragma unroll
        for (int j = 0; j < 4; j++)
#pragma unroll
            for (int r = 0; r < 4; r++) acc[i][j][r] = 0.f;

    int nt = K / BK;

#define HISSUE(tile, stage)                                                     \
    do {                                                                        \
        int kb_ = (tile) * BK;                                                  \
        uint32_t so_ = (uint32_t)((stage) * STAGE_BYTES);                       \
        _Pragma("unroll")                                                       \
        for (int ii = 0; ii < AT; ii++)                                         \
            cp16(dA[ii] + so_, Ag + (size_t)rA[ii] * K + kb_ + cA[ii], szA[ii]);\
        _Pragma("unroll")                                                       \
        for (int ii = 0; ii < 4; ii++)                                          \
            cp16(dB[ii] + so_, Bg + (size_t)rB[ii] * K + kb_ + cB[ii], 16);     \
    } while (0)

#pragma unroll
    for (int s = 0; s < STG - 1; s++) {
        if (s < nt) HISSUE(s, s);
        asm volatile("cp.async.commit_group;");
    }

    int stage = 0;
    for (int t = 0; t < nt; t++) {
        asm volatile("cp.async.wait_group %0;" :: "n"(STG - 2));
        __syncthreads();

        int ntile = t + STG - 1;
        int nstage = stage + STG - 1;
        if (nstage >= STG) nstage -= STG;
        if (ntile < nt) HISSUE(ntile, nstage);
        asm volatile("cp.async.commit_group;");

        uint32_t stg = sbase + (uint32_t)(stage * STAGE_BYTES);

#pragma unroll
        for (int kk = 0; kk < 4; kk++) {
            uint32_t kby = (uint32_t)(kk * 16 * 2);
            uint32_t af[AT][4], bfr[2][4];
#pragma unroll
            for (int i = 0; i < AT; i++)
                ldsm4(af[i], stg + aOff + (uint32_t)(i * 16 * BKH * 2) + kby);
#pragma unroll
            for (int jp = 0; jp < 2; jp++)
                ldsm4(bfr[jp], stg + bOff + (uint32_t)(jp * 16 * BKH * 2) + kby);
#pragma unroll
            for (int j = 0; j < 4; j++) {
                uint32_t b0 = bfr[j >> 1][(j & 1) * 2];
                uint32_t b1 = bfr[j >> 1][(j & 1) * 2 + 1];
#pragma unroll
                for (int i = 0; i < AT; i++) mma_f16(acc[i][j], af[i], b0, b1);
            }
        }
        if (++stage == STG) stage = 0;
    }
#undef HISSUE

    float cs[4][2], cb[4][2], cm[4][2];
    if (mode == 1) {
#pragma unroll
        for (int j = 0; j < 4; j++) {
            int c = tileN + wn + j * 8 + t4 * 2;
#pragma unroll
            for (int q = 0; q < 2; q++) {
                cs[j][q] = gv[c + q] * rsqrtf(vv[c + q] + 1e-5f);
                cb[j][q] = bv[c + q];
                cm[j][q] = mv[c + q];
            }
        }
    }

#pragma unroll
    for (int i = 0; i < AT; i++) {
#pragma unroll
        for (int h8 = 0; h8 < 2; h8++) {
            int r = tileM + wm + i * 16 + g8 + h8 * 8;
            if (r >= M) continue;
#pragma unroll
            for (int j = 0; j < 4; j++) {
                int c = tileN + wn + j * 8 + t4 * 2;
                float v0 = acc[i][j][h8 * 2 + 0];
                float v1 = acc[i][j][h8 * 2 + 1];
                if (mode == 1) {
                    v0 = fmaxf((v0 - cm[j][0]) * cs[j][0] + cb[j][0], 0.f);
                    v1 = fmaxf((v1 - cm[j][1]) * cs[j][1] + cb[j][1], 0.f);
                    __half2 hv;
                    hv.x = __float2half(v0);
                    hv.y = __float2half(v1);
                    *(__half2*)(Ch + (size_t)r * Ncols + c) = hv;
                } else if (mode == 2) {
                    v0 = v0 > 0.f ? v0 : 0.01f * v0;
                    v1 = v1 > 0.f ? v1 : 0.01f * v1;
                    __half2 hv;
                    hv.x = __float2half(v0);
                    hv.y = __float2half(v1);
                    *(__half2*)(Ch + (size_t)r * Ncols + c) = hv;
                } else if (mode == 3) {
                    __half2 hv;
                    hv.x = __float2half(v0);
                    hv.y = __float2half(v1);
                    *(__half2*)(Ch + (size_t)r * Ncols + c) = hv;
                } else {
                    *(float2*)(Cf + (size_t)r * Ncols + c) = make_float2(v0, v1);
                }
            }
        }
    }
}

#define DSMEM4 (STG * (128 * BKH * 2 + TILE_B_BYTES))   // 110592
#define DSMEM2 (STG * (64 * BKH * 2 + TILE_B_BYTES))    // 82944

// ---------------- host orchestration (single stream) ----------------
extern "C" void kernel_launch(void* const* d_in, const int* in_sizes, int n_in,
                              void* d_out, int out_size) {
    const float* x  = (const float*)d_in[0];
    const int*   ei = (const int*)d_in[1];
    const float* ea = (const float*)d_in[2];
    int base = 3;
    if (n_in > 19) base = 3 + (n_in - 19);
    const float* l0_src  = (const float*)d_in[base + 0];
    const float* l0_dst  = (const float*)d_in[base + 1];
    const float* l0_edge = (const float*)d_in[base + 2];
    const float* l0_w1   = (const float*)d_in[base + 3];
    const float* l0_g    = (const float*)d_in[base + 4];
    const float* l0_b    = (const float*)d_in[base + 5];
    const float* l0_m    = (const float*)d_in[base + 6];
    const float* l0_v    = (const float*)d_in[base + 7];
    const float* l0_w2   = (const float*)d_in[base + 8];
    const float* l1_edge = (const float*)d_in[base + 9];
    const float* l1_w1   = (const float*)d_in[base + 10];
    const float* l1_g    = (const float*)d_in[base + 11];
    const float* l1_b    = (const float*)d_in[base + 12];
    const float* l1_m    = (const float*)d_in[base + 13];
    const float* l1_v    = (const float*)d_in[base + 14];
    const float* l1_w2   = (const float*)d_in[base + 15];
    float* out = (float*)d_out;

    __half *sfdf, *x1h, *xh, *ob, *hb, *wcat, *w01, *w02c, *w11, *w12c;
    int *rowptr, *cursor, *eidx;
    cudaGetSymbolAddress((void**)&sfdf, g_sfdf);
    cudaGetSymbolAddress((void**)&x1h, g_x1);
    cudaGetSymbolAddress((void**)&xh, g_xh);
    cudaGetSymbolAddress((void**)&ob, g_ob);
    cudaGetSymbolAddress((void**)&hb, g_hb);
    cudaGetSymbolAddress((void**)&wcat, g_wcat);
    cudaGetSymbolAddress((void**)&w01, g_w01);
    cudaGetSymbolAddress((void**)&w02c, g_w02c);
    cudaGetSymbolAddress((void**)&w11, g_w11);
    cudaGetSymbolAddress((void**)&w12c, g_w12c);
    cudaGetSymbolAddress((void**)&rowptr, g_rowptr);
    cudaGetSymbolAddress((void**)&cursor, g_cursor);
    cudaGetSymbolAddress((void**)&eidx, g_eidx);

    cudaFuncSetAttribute(k_hgemm<4>, cudaFuncAttributeMaxDynamicSharedMemorySize, DSMEM4);
    cudaFuncSetAttribute(k_hgemm<2>, cudaFuncAttributeMaxDynamicSharedMemorySize, DSMEM2);

    const int* dstBoth = ei + ETOT;
    const int BIG = 1 << 30;

    dim3 blk(256);
    int gy = (NN + 127) / 128;      // 157
    int gy64 = (NN + 63) / 64;      // 313
    dim3 gproj(2048 / BN, gy), g512_64(HC / BN, gy64), g2048(2048 / BN, gy);

    // ---- conversions needed by proj first (so proj GEMM is launch #4 for ncu) ---
    k_half<<<(NN * FINC + 255) / 256, 256>>>(x, xh, NN * FINC);
    k_half_cat2<<<(4 * HC * FINC + 255) / 256, 256>>>(l0_src, l0_dst, wcat);
    k_half2x<<<(4 * H2C * HC + 255) / 256, 256>>>(l0_w1, w01, l1_w1, w11, 2 * H2C * HC);

    // ---- layer 0 projection GEMM (launch #4) ----
    k_hgemm<4><<<gproj, blk, DSMEM4>>>(xh, xh, BIG, wcat, NN, FINC, 2048, 3,
                                       nullptr, nullptr, nullptr, nullptr, nullptr, sfdf);

    // ---- remaining conversions + CSR build (independent of proj) ----
    k_half_w2cat2<<<(4 * HC * H2C + 255) / 256, 256>>>(l0_w2, w02c, l1_w2, w12c);
    k_zero_int<<<(2 * NN + 255) / 256, 256>>>(cursor, 2 * NN);
    k_count_deg2<<<(2 * LPART + 255) / 256, 256>>>(dstBoth, cursor);
    k_scan2<<<2, 1024>>>(cursor, rowptr);
    k_copy_rp2<<<(2 * NN + 255) / 256, 256>>>(rowptr, cursor);
    k_scatter2<<<(2 * LPART + 255) / 256, 256>>>(dstBoth, cursor, eidx);
    k_sort_buckets2<<<(2 * NN + 127) / 128, 128>>>(rowptr, eidx);

    // ---- layer 0 ----
    k_agg2<<<(2 * NN) / 4, 128>>>(sfdf, 1024, 2048, sfdf + 512, 1024, 2048,
                                  l0_edge, ea, ei, rowptr, eidx, ob);
    k_hgemm<4><<<g2048, blk, DSMEM4>>>(ob, ob + (size_t)NN * HC, 1024, w01,
                                       NN, HC, 2048, 1, l0_g, l0_b, l0_m, l0_v,
                                       nullptr, hb);
    k_hgemm<2><<<g512_64, blk, DSMEM2>>>(hb, hb, BIG, w02c, NN, 2048, HC, 2,
                                         nullptr, nullptr, nullptr, nullptr, nullptr, x1h);

    // ---- layer 1 ----
    k_agg2<<<(2 * NN) / 4, 128>>>(x1h, 0, HC, x1h, 0, HC,
                                  l1_edge, ea, ei, rowptr, eidx, ob);
    k_hgemm<4><<<g2048, blk, DSMEM4>>>(ob, ob + (size_t)NN * HC, 1024, w11,
                                       NN, HC, 2048, 1, l1_g, l1_b, l1_m, l1_v,
                                       nullptr, hb);
    k_hgemm<2><<<g512_64, blk, DSMEM2>>>(hb, hb, BIG, w12c, NN, 2048, HC, 0,
                                         nullptr, nullptr, nullptr, nullptr, out, nullptr);
}

// round 16
// speedup vs baseline: 1.0927x; 1.0927x over previous
// Round 16: clean resubmit of round 15 (AT=3 W2 tiles) after unexplained
// container failure — design audit found no defect; distinguishing infra
// flake from an AT=3-specific problem.
#include <cuda_runtime.h>
#include <cuda_fp16.h>
#include <math.h>
#include <stdint.h>

#define NN 20000
#define ETOT 150000
#define LPART 75000
#define FINC 256
#define HC 512
#define H2C 1024

// ---------------- static device scratch ----------------
__device__ __half g_sfdf[NN * 2048];
__device__ __half g_x1[NN * HC];
__device__ __half g_xh[NN * FINC];
__device__ __half g_ob[2 * NN * HC];
__device__ __half g_hb[NN * 2048];
__device__ __half g_wcat[2048 * FINC];
__device__ __half g_w01[2 * H2C * HC];
__device__ __half g_w02c[HC * 2048];
__device__ __half g_w11[2 * H2C * HC];
__device__ __half g_w12c[HC * 2048];
__device__ int g_rowptr[2][NN + 1];
__device__ int g_cursor[2][NN];
__device__ int g_eidx[2][LPART];

// ---------------- CSR build ----------------
__global__ void k_zero_int(int* p, int n) {
    int i = blockIdx.x * blockDim.x + threadIdx.x;
    if (i < n) p[i] = 0;
}

__global__ void k_count_deg2(const int* __restrict__ dstBoth, int* __restrict__ deg) {
    int i = blockIdx.x * blockDim.x + threadIdx.x;
    if (i < 2 * LPART) {
        int p = i / LPART;
        atomicAdd(&deg[p * NN + dstBoth[i]], 1);
    }
}

__global__ void k_scan2(const int* __restrict__ deg, int* __restrict__ rowptr) {
    __shared__ int sbuf[1024];
    __shared__ int carry;
    int p = blockIdx.x;
    const int* d = deg + p * NN;
    int* rp = rowptr + p * (NN + 1);
    int t = threadIdx.x;
    if (t == 0) { carry = 0; rp[0] = 0; }
    __syncthreads();
    for (int base = 0; base < NN; base += 1024) {
        int v = (base + t < NN) ? d[base + t] : 0;
        sbuf[t] = v;
        __syncthreads();
        for (int off = 1; off < 1024; off <<= 1) {
            int nv = (t >= off) ? sbuf[t - off] : 0;
            __syncthreads();
            sbuf[t] += nv;
            __syncthreads();
        }
        if (base + t < NN) rp[base + t + 1] = carry + sbuf[t];
        __syncthreads();
        if (t == 0) carry += sbuf[1023];
        __syncthreads();
    }
}

__global__ void k_copy_rp2(const int* __restrict__ rowptr, int* __restrict__ cursor) {
    int i = blockIdx.x * blockDim.x + threadIdx.x;
    if (i < 2 * NN) {
        int p = i / NN, r = i % NN;
        cursor[i] = rowptr[p * (NN + 1) + r];
    }
}

__global__ void k_scatter2(const int* __restrict__ dstBoth, int* __restrict__ cursor,
                           int* __restrict__ eidx) {
    int i = blockIdx.x * blockDim.x + threadIdx.x;
    if (i < 2 * LPART) {
        int p = i / LPART;
        int pos = atomicAdd(&cursor[p * NN + dstBoth[i]], 1);
        eidx[p * LPART + pos] = i - p * LPART;
    }
}

__global__ void k_sort_buckets2(const int* __restrict__ rowptr, int* __restrict__ eidx) {
    int i = blockIdx.x * blockDim.x + threadIdx.x;
    if (i >= 2 * NN) return;
    int p = i / NN, node = i % NN;
    const int* rp = rowptr + p * (NN + 1);
    int* ex = eidx + p * LPART;
    int a = rp[node], b = rp[node + 1];
    for (int q = a + 1; q < b; q++) {
        int key = ex[q];
        int j = q - 1;
        while (j >= a && ex[j] > key) { ex[j + 1] = ex[j]; j--; }
        ex[j + 1] = key;
    }
}

// ---------------- fused conversions ----------------
__global__ void k_half(const float* __restrict__ s, __half* __restrict__ h, int n) {
    int i = blockIdx.x * blockDim.x + threadIdx.x;
    if (i < n) h[i] = __float2half(s[i]);
}

__global__ void k_half_cat2(const float* __restrict__ ssrc, const float* __restrict__ sdst,
                            __half* __restrict__ wcat) {
    int i = blockIdx.x * blockDim.x + threadIdx.x;
    int NEL = 2 * HC * FINC;
    if (i >= 2 * NEL) return;
    int which = i >= NEL;
    int ii = i - which * NEL;
    const float* s = which ? sdst : ssrc;
    int off = which ? 512 : 0;
    int l = ii >> 17;
    int rem = ii & 131071;
    int rr = rem >> 8;
    int c = rem & 255;
    wcat[((l * 1024 + off + rr) << 8) + c] = __float2half(s[ii]);
}

__global__ void k_half2x(const float* __restrict__ s0, __half* __restrict__ h0,
                         const float* __restrict__ s1, __half* __restrict__ h1, int n) {
    int i = blockIdx.x * blockDim.x + threadIdx.x;
    if (i < n) h0[i] = __float2half(s0[i]);
    else if (i < 2 * n) h1[i - n] = __float2half(s1[i - n]);
}

__global__ void k_half_w2cat2(const float* __restrict__ s0, __half* __restrict__ w0,
                              const float* __restrict__ s1, __half* __restrict__ w1) {
    int i = blockIdx.x * blockDim.x + threadIdx.x;
    int NEL = 2 * HC * H2C;
    if (i >= 2 * NEL) return;
    int which = i >= NEL;
    int ii = i - which * NEL;
    const float* s = which ? s1 : s0;
    __half* w = which ? w1 : w0;
    int l = ii >> 19;
    int rem = ii & 524287;
    int n = rem >> 10;
    int kk = rem & 1023;
    w[n * 2048 + (l << 10) + kk] = __float2half(s[ii]);
}

// ---------------- merged per-layer edge softmax aggregation (int4) ---------------
__global__ __launch_bounds__(128) void k_agg2(
    const __half* __restrict__ sf_base, int sf_loff, int sstr,
    const __half* __restrict__ df_base, int df_loff, int dstr,
    const float* __restrict__ WeBoth,
    const float* __restrict__ ea,
    const int* __restrict__ srcBoth,
    const int* __restrict__ rowptr,
    const int* __restrict__ eidx,
    __half* __restrict__ oh)
{
    __shared__ float wsh[HC];
    int t = threadIdx.x;
    int pblk = (blockIdx.x * 4) / NN;
    for (int i = t; i < HC; i += 128) wsh[i] = WeBoth[pblk * HC + i];
    __syncthreads();

    int warp = t >> 5, lane = t & 31;
    int gw = blockIdx.x * 4 + warp;
    if (gw >= 2 * NN) return;
    int p = gw >= NN;
    int node = gw - p * NN;

    const int4* sfeat = (const int4*)(sf_base + (size_t)p * sf_loff);
    const int4* dfeat = (const int4*)(df_base + (size_t)p * df_loff);
    int s4 = sstr >> 3, d4 = dstr >> 3;
    const float* eap = ea + (size_t)p * LPART;
    const int* srcp = srcBoth + (size_t)p * LPART;
    const int* rp = rowptr + p * (NN + 1);
    const int* ex = eidx + (size_t)p * LPART;

    float wv[16];
#pragma unroll
    for (int k = 0; k < 8; k++) {
        wv[k] = wsh[8 * lane + k];
        wv[8 + k] = wsh[8 * (lane + 32) + k];
    }

    float m[16], s[16], tt[16];
#pragma unroll
    for (int j = 0; j < 16; j++) { m[j] = -INFINITY; s[j] = 0.f; tt[j] = 0.f; }

    int e0 = rp[node], e1 = rp[node + 1];
    for (int e = e0; e < e1; e++) {
        int eid = ex[e];
        int sidx = srcp[eid];
        float a = eap[eid];
        const int4* row = sfeat + (size_t)sidx * s4;
        int4 v0 = row[lane];
        int4 v1 = row[lane + 32];
        const __half2* h0 = (const __half2*)&v0;
        const __half2* h1 = (const __half2*)&v1;
#pragma unroll
        for (int q = 0; q < 4; q++) {
            float2 f0 = __half22float2(h0[q]);
            float2 f1 = __half22float2(h1[q]);
            float vals[4] = {f0.x, f0.y, f1.x, f1.y};
            int js[4] = {2 * q, 2 * q + 1, 8 + 2 * q, 8 + 2 * q + 1};
#pragma unroll
            for (int u = 0; u < 4; u++) {
                int j = js[u];
                float msg = fmaxf(vals[u] + a * wv[j], 0.f) + 1e-7f;
                float mn = fmaxf(m[j], msg);
                float scale = __expf(m[j] - mn);
                float pr = __expf(msg - mn);
                s[j] = s[j] * scale + pr;
                tt[j] = tt[j] * scale + msg * pr;
                m[j] = mn;
            }
        }
    }

    const int4* drow = dfeat + (size_t)node * d4;
    int4 d0 = drow[lane];
    int4 d1 = drow[lane + 32];
    const __half2* dh0 = (const __half2*)&d0;
    const __half2* dh1 = (const __half2*)&d1;

    int4 o0, o1;
    __half2* oh0 = (__half2*)&o0;
    __half2* oh1 = (__half2*)&o1;
#pragma unroll
    for (int q = 0; q < 4; q++) {
        float2 dv0 = __half22float2(dh0[q]);
        float2 dv1 = __half22float2(dh1[q]);
        float a0 = tt[2 * q] / (s[2 * q] + 1e-16f) + dv0.x;
        float a1 = tt[2 * q + 1] / (s[2 * q + 1] + 1e-16f) + dv0.y;
        float b0 = tt[8 + 2 * q] / (s[8 + 2 * q] + 1e-16f) + dv1.x;
        float b1 = tt[8 + 2 * q + 1] / (s[8 + 2 * q + 1] + 1e-16f) + dv1.y;
        oh0[q] = __floats2half2_rn(a0, a1);
        oh1[q] = __floats2half2_rn(b0, b1);
    }
    int4* orow = (int4*)(oh + ((size_t)p * NN + node) * HC);
    orow[lane] = o0;
    orow[lane + 32] = o1;
}

// ---------------- fp16 GEMM, templated on M-tile: BM = AT*32 ---------------------
#define BN 128
#define BK 64
#define BKH 72
#define STG 3
#define TILE_B_BYTES (BN * BKH * 2)

__device__ __forceinline__ void mma_f16(float* c, const uint32_t* a, uint32_t b0, uint32_t b1) {
    asm volatile(
        "mma.sync.aligned.m16n8k16.row.col.f32.f16.f16.f32 "
        "{%0,%1,%2,%3}, {%4,%5,%6,%7}, {%8,%9}, {%0,%1,%2,%3};"
        : "+f"(c[0]), "+f"(c[1]), "+f"(c[2]), "+f"(c[3])
        : "r"(a[0]), "r"(a[1]), "r"(a[2]), "r"(a[3]), "r"(b0), "r"(b1));
}

__device__ __forceinline__ void ldsm4(uint32_t* r, uint32_t addr) {
    asm volatile("ldmatrix.sync.aligned.m8n8.x4.shared.b16 {%0,%1,%2,%3}, [%4];"
                 : "=r"(r[0]), "=r"(r[1]), "=r"(r[2]), "=r"(r[3]) : "r"(addr));
}

__device__ __forceinline__ void cp16(uint32_t saddr, const void* gaddr, int srcbytes) {
    asm volatile("cp.async.cg.shared.global [%0], [%1], 16, %2;"
                 :: "r"(saddr), "l"(gaddr), "r"(srcbytes));
}

template <int AT>
__global__ __launch_bounds__(256, 2) void k_hgemm(
    const __half* __restrict__ A0, const __half* __restrict__ A1, int nsplit,
    const __half* __restrict__ B,
    int M, int K, int Ncols, int mode,
    const float* __restrict__ gv, const float* __restrict__ bv,
    const float* __restrict__ mv, const float* __restrict__ vv,
    float* __restrict__ Cf, __half* __restrict__ Ch)
{
    constexpr int BMt = AT * 32;
    constexpr int TILE_A_BYTES = BMt * BKH * 2;
    constexpr int STAGE_BYTES = TILE_A_BYTES + TILE_B_BYTES;

    extern __shared__ __align__(128) char smc[];
    uint32_t sbase = (uint32_t)__cvta_generic_to_shared(smc);

    int tid = threadIdx.x;
    int tileM = blockIdx.y * BMt, tileN = blockIdx.x * BN;
    const __half* A = (tileN >= nsplit) ? A1 : A0;
    int warp = tid >> 5, lane = tid & 31;
    int g8 = lane >> 2, t4 = lane & 3;
    int wm = (warp & 1) * (AT * 16);
    int wn = (warp >> 1) * 32;

    const __half* Ag = A + (size_t)tileM * K;
    const __half* Bg = B + (size_t)tileN * K;

    int rA[AT], cA[AT], szA[AT];
    uint32_t dA[AT];
#pragma unroll
    for (int i = 0; i < AT; i++) {
        int q = tid + i * 256;
        rA[i] = q >> 3;
        cA[i] = (q & 7) * 8;
        szA[i] = (tileM + rA[i]) < M ? 16 : 0;
        dA[i] = sbase + (uint32_t)((rA[i] * BKH + cA[i]) * 2);
    }
    int rB[4], cB[4];
    uint32_t dB[4];
#pragma unroll
    for (int i = 0; i < 4; i++) {
        int q = tid + i * 256;
        rB[i] = q >> 3;
        cB[i] = (q & 7) * 8;
        dB[i] = sbase + (uint32_t)(TILE_A_BYTES + (rB[i] * BKH + cB[i]) * 2);
    }

    int mrowA = (lane & 7) + ((lane >> 3) & 1) * 8;
    int kcolA = (lane >> 4) * 8;
    uint32_t aOff = (uint32_t)(((wm + mrowA) * BKH + kcolA) * 2);
    int nrowB = ((lane >> 4) & 1) * 8 + (lane & 7);
    int kcolB = ((lane >> 3) & 1) * 8;
    uint32_t bOff = (uint32_t)(TILE_A_BYTES + ((wn + nrowB) * BKH + kcolB) * 2);

    float acc[AT][4][4];
#pragma unroll
    for (int i = 0; i < AT; i++)
#pragma unroll
        for (int j = 0; j < 4; j++)
#pragma unroll
            for (int r = 0; r < 4; r++) acc[i][j][r] = 0.f;

    int nt = K / BK;

#define HISSUE(tile, stage)                                                     \
    do {                                                                        \
        int kb_ = (tile) * BK;                                                  \
        uint32_t so_ = (uint32_t)((stage) * STAGE_BYTES);                       \
        _Pragma("unroll")                                                       \
        for (int ii = 0; ii < AT; ii++)                                         \
            cp16(dA[ii] + so_, Ag + (size_t)rA[ii] * K + kb_ + cA[ii], szA[ii]);\
        _Pragma("unroll")                                                       \
        for (int ii = 0; ii < 4; ii++)                                          \
            cp16(dB[ii] + so_, Bg + (size_t)rB[ii] * K + kb_ + cB[ii], 16);     \
    } while (0)

#pragma unroll
    for (int s = 0; s < STG - 1; s++) {
        if (s < nt) HISSUE(s, s);
        asm volatile("cp.async.commit_group;");
    }

    int stage = 0;
    for (int t = 0; t < nt; t++) {
        asm volatile("cp.async.wait_group %0;" :: "n"(STG - 2));
        __syncthreads();

        int ntile = t + STG - 1;
        int nstage = stage + STG - 1;
        if (nstage >= STG) nstage -= STG;
        if (ntile < nt) HISSUE(ntile, nstage);
        asm volatile("cp.async.commit_group;");

        uint32_t stg = sbase + (uint32_t)(stage * STAGE_BYTES);

#pragma unroll
        for (int kk = 0; kk < 4; kk++) {
            uint32_t kby = (uint32_t)(kk * 16 * 2);
            uint32_t af[AT][4], bfr[2][4];
#pragma unroll
            for (int i = 0; i < AT; i++)
                ldsm4(af[i], stg + aOff + (uint32_t)(i * 16 * BKH * 2) + kby);
#pragma unroll
            for (int jp = 0; jp < 2; jp++)
                ldsm4(bfr[jp], stg + bOff + (uint32_t)(jp * 16 * BKH * 2) + kby);
#pragma unroll
            for (int j = 0; j < 4; j++) {
                uint32_t b0 = bfr[j >> 1][(j & 1) * 2];
                uint32_t b1 = bfr[j >> 1][(j & 1) * 2 + 1];
#pragma unroll
                for (int i = 0; i < AT; i++) mma_f16(acc[i][j], af[i], b0, b1);
            }
        }
        if (++stage == STG) stage = 0;
    }
#undef HISSUE

    float cs[4][2], cb[4][2], cm[4][2];
    if (mode == 1) {
#pragma unroll
        for (int j = 0; j < 4; j++) {
            int c = tileN + wn + j * 8 + t4 * 2;
#pragma unroll
            for (int q = 0; q < 2; q++) {
                cs[j][q] = gv[c + q] * rsqrtf(vv[c + q] + 1e-5f);
                cb[j][q] = bv[c + q];
                cm[j][q] = mv[c + q];
            }
        }
    }

#pragma unroll
    for (int i = 0; i < AT; i++) {
#pragma unroll
        for (int h8 = 0; h8 < 2; h8++) {
            int r = tileM + wm + i * 16 + g8 + h8 * 8;
            if (r >= M) continue;
#pragma unroll
            for (int j = 0; j < 4; j++) {
                int c = tileN + wn + j * 8 + t4 * 2;
                float v0 = acc[i][j][h8 * 2 + 0];
                float v1 = acc[i][j][h8 * 2 + 1];
                if (mode == 1) {
                    v0 = fmaxf((v0 - cm[j][0]) * cs[j][0] + cb[j][0], 0.f);
                    v1 = fmaxf((v1 - cm[j][1]) * cs[j][1] + cb[j][1], 0.f);
                    __half2 hv;
                    hv.x = __float2half(v0);
                    hv.y = __float2half(v1);
                    *(__half2*)(Ch + (size_t)r * Ncols + c) = hv;
                } else if (mode == 2) {
                    v0 = v0 > 0.f ? v0 : 0.01f * v0;
                    v1 = v1 > 0.f ? v1 : 0.01f * v1;
                    __half2 hv;
                    hv.x = __float2half(v0);
                    hv.y = __float2half(v1);
                    *(__half2*)(Ch + (size_t)r * Ncols + c) = hv;
                } else if (mode == 3) {
                    __half2 hv;
                    hv.x = __float2half(v0);
                    hv.y = __float2half(v1);
                    *(__half2*)(Ch + (size_t)r * Ncols + c) = hv;
                } else {
                    *(float2*)(Cf + (size_t)r * Ncols + c) = make_float2(v0, v1);
                }
            }
        }
    }
}

#define DSMEM4 (STG * (128 * BKH * 2 + TILE_B_BYTES))   // 110592
#define DSMEM3 (STG * (96 * BKH * 2 + TILE_B_BYTES))    // 96768

// ---------------- host orchestration (single stream) ----------------
extern "C" void kernel_launch(void* const* d_in, const int* in_sizes, int n_in,
                              void* d_out, int out_size) {
    const float* x  = (const float*)d_in[0];
    const int*   ei = (const int*)d_in[1];
    const float* ea = (const float*)d_in[2];
    int base = 3;
    if (n_in > 19) base = 3 + (n_in - 19);
    const float* l0_src  = (const float*)d_in[base + 0];
    const float* l0_dst  = (const float*)d_in[base + 1];
    const float* l0_edge = (const float*)d_in[base + 2];
    const float* l0_w1   = (const float*)d_in[base + 3];
    const float* l0_g    = (const float*)d_in[base + 4];
    const float* l0_b    = (const float*)d_in[base + 5];
    const float* l0_m    = (const float*)d_in[base + 6];
    const float* l0_v    = (const float*)d_in[base + 7];
    const float* l0_w2   = (const float*)d_in[base + 8];
    const float* l1_edge = (const float*)d_in[base + 9];
    const float* l1_w1   = (const float*)d_in[base + 10];
    const float* l1_g    = (const float*)d_in[base + 11];
    const float* l1_b    = (const float*)d_in[base + 12];
    const float* l1_m    = (const float*)d_in[base + 13];
    const float* l1_v    = (const float*)d_in[base + 14];
    const float* l1_w2   = (const float*)d_in[base + 15];
    float* out = (float*)d_out;

    __half *sfdf, *x1h, *xh, *ob, *hb, *wcat, *w01, *w02c, *w11, *w12c;
    int *rowptr, *cursor, *eidx;
    cudaGetSymbolAddress((void**)&sfdf, g_sfdf);
    cudaGetSymbolAddress((void**)&x1h, g_x1);
    cudaGetSymbolAddress((void**)&xh, g_xh);
    cudaGetSymbolAddress((void**)&ob, g_ob);
    cudaGetSymbolAddress((void**)&hb, g_hb);
    cudaGetSymbolAddress((void**)&wcat, g_wcat);
    cudaGetSymbolAddress((void**)&w01, g_w01);
    cudaGetSymbolAddress((void**)&w02c, g_w02c);
    cudaGetSymbolAddress((void**)&w11, g_w11);
    cudaGetSymbolAddress((void**)&w12c, g_w12c);
    cudaGetSymbolAddress((void**)&rowptr, g_rowptr);
    cudaGetSymbolAddress((void**)&cursor, g_cursor);
    cudaGetSymbolAddress((void**)&eidx, g_eidx);

    cudaFuncSetAttribute(k_hgemm<4>, cudaFuncAttributeMaxDynamicSharedMemorySize, DSMEM4);
    cudaFuncSetAttribute(k_hgemm<3>, cudaFuncAttributeMaxDynamicSharedMemorySize, DSMEM3);

    const int* dstBoth = ei + ETOT;
    const int BIG = 1 << 30;

    dim3 blk(256);
    int gy = (NN + 127) / 128;      // 157
    int gy96 = (NN + 95) / 96;      // 209
    dim3 gproj(2048 / BN, gy), g512_96(HC / BN, gy96), g2048(2048 / BN, gy);

    // ---- conversions needed by proj first ----
    k_half<<<(NN * FINC + 255) / 256, 256>>>(x, xh, NN * FINC);
    k_half_cat2<<<(4 * HC * FINC + 255) / 256, 256>>>(l0_src, l0_dst, wcat);
    k_half2x<<<(4 * H2C * HC + 255) / 256, 256>>>(l0_w1, w01, l1_w1, w11, 2 * H2C * HC);

    // ---- layer 0 projection GEMM ----
    k_hgemm<4><<<gproj, blk, DSMEM4>>>(xh, xh, BIG, wcat, NN, FINC, 2048, 3,
                                       nullptr, nullptr, nullptr, nullptr, nullptr, sfdf);

    // ---- remaining conversions + CSR build ----
    k_half_w2cat2<<<(4 * HC * H2C + 255) / 256, 256>>>(l0_w2, w02c, l1_w2, w12c);
    k_zero_int<<<(2 * NN + 255) / 256, 256>>>(cursor, 2 * NN);
    k_count_deg2<<<(2 * LPART + 255) / 256, 256>>>(dstBoth, cursor);
    k_scan2<<<2, 1024>>>(cursor, rowptr);
    k_copy_rp2<<<(2 * NN + 255) / 256, 256>>>(rowptr, cursor);
    k_scatter2<<<(2 * LPART + 255) / 256, 256>>>(dstBoth, cursor, eidx);
    k_sort_buckets2<<<(2 * NN + 127) / 128, 128>>>(rowptr, eidx);

    // ---- layer 0 ----
    k_agg2<<<(2 * NN) / 4, 128>>>(sfdf, 1024, 2048, sfdf + 512, 1024, 2048,
                                  l0_edge, ea, ei, rowptr, eidx, ob);
    k_hgemm<4><<<g2048, blk, DSMEM4>>>(ob, ob + (size_t)NN * HC, 1024, w01,
                                       NN, HC, 2048, 1, l0_g, l0_b, l0_m, l0_v,
                                       nullptr, hb);
    k_hgemm<3><<<g512_96, blk, DSMEM3>>>(hb, hb, BIG, w02c, NN, 2048, HC, 2,
                                         nullptr, nullptr, nullptr, nullptr, nullptr, x1h);

    // ---- layer 1 ----
    k_agg2<<<(2 * NN) / 4, 128>>>(x1h, 0, HC, x1h, 0, HC,
                                  l1_edge, ea, ei, rowptr, eidx, ob);
    k_hgemm<4><<<g2048, blk, DSMEM4>>>(ob, ob + (size_t)NN * HC, 1024, w11,
                                       NN, HC, 2048, 1, l1_g, l1_b, l1_m, l1_v,
                                       nullptr, hb);
    k_hgemm<3><<<g512_96, blk, DSMEM3>>>(hb, hb, BIG, w12c, NN, 2048, HC, 0,
                                         nullptr, nullptr, nullptr, nullptr, out, nullptr);
}